// round 1
// baseline (speedup 1.0000x reference)
#include <cuda_runtime.h>

#define Bn 16
#define Cn 512
#define Ln 2048
#define Dn 64

// Scratch (device globals — no allocations allowed in kernel_launch)
__device__ float g_q[(size_t)Bn * Ln * Dn];            //  8.4 MB  [B][L][D]
__device__ float g_k[(size_t)Bn * Ln * Dn];            //  8.4 MB  [B][L][D]
__device__ float g_v[(size_t)Bn * Ln * Cn];            // 67   MB  [B][L][C]
__device__ float g_attn[(size_t)Bn * Ln * Ln];         // 268  MB  [B][L][L]
__device__ float g_av[(size_t)Bn * Ln * Cn];           // 67   MB  [B][L][C]

// ---------------------------------------------------------------------------
// Kernel 1: conv1x1 to [B, L, O] layout.
// y[b][l][o] = sum_c w[o][c] * x[b][c][l] + bias[o]
// grid: (L/64, O/64, B), 256 threads, 4x4 micro-tile per thread.
// ---------------------------------------------------------------------------
__global__ void __launch_bounds__(256) conv_blo_kernel(
    const float* __restrict__ x, const float* __restrict__ w,
    const float* __restrict__ bias, float* __restrict__ y, int O)
{
    __shared__ float Xs[16][64];   // Xs[c][l]  (natural, coalesced)
    __shared__ float Ws[16][68];   // Ws[c][o]  (transposed on load, pad 68 keeps 16B align)

    const int b  = blockIdx.z;
    const int l0 = blockIdx.x * 64;
    const int o0 = blockIdx.y * 64;
    const int t  = threadIdx.x;
    const int ox = t & 15;          // output-channel group (contiguous store dim)
    const int ly = t >> 4;          // l group

    const float* xb = x + (size_t)b * Cn * Ln;
    float acc[4][4] = {};           // acc[li][oi]

    for (int c0 = 0; c0 < Cn; c0 += 16) {
#pragma unroll
        for (int j = 0; j < 4; j++) {
            int i  = t + j * 256;
            int cc = i >> 6, ll = i & 63;
            Xs[cc][ll] = xb[(size_t)(c0 + cc) * Ln + l0 + ll];
            int oo = i >> 4, kc = i & 15;
            Ws[kc][oo] = w[(o0 + oo) * Cn + c0 + kc];
        }
        __syncthreads();
#pragma unroll
        for (int kc = 0; kc < 16; kc++) {
            float4 xv = *(const float4*)&Xs[kc][ly * 4];
            float4 wv = *(const float4*)&Ws[kc][ox * 4];
            float xa[4] = {xv.x, xv.y, xv.z, xv.w};
            float wa[4] = {wv.x, wv.y, wv.z, wv.w};
#pragma unroll
            for (int li = 0; li < 4; li++)
#pragma unroll
                for (int oi = 0; oi < 4; oi++)
                    acc[li][oi] += xa[li] * wa[oi];
        }
        __syncthreads();
    }

    float4 bv4 = *(const float4*)&bias[o0 + ox * 4];
    float ba[4] = {bv4.x, bv4.y, bv4.z, bv4.w};
#pragma unroll
    for (int li = 0; li < 4; li++) {
        int l = l0 + ly * 4 + li;
        float4 r;
        r.x = acc[li][0] + ba[0];
        r.y = acc[li][1] + ba[1];
        r.z = acc[li][2] + ba[2];
        r.w = acc[li][3] + ba[3];
        *(float4*)&y[((size_t)b * Ln + l) * O + o0 + ox * 4] = r;
    }
}

// ---------------------------------------------------------------------------
// Kernel 2: scores S[b][l][m] = sum_d Q[b][l][d] * K[b][m][d]
// grid: (L/64, L/64, B), 256 threads.
// ---------------------------------------------------------------------------
__global__ void __launch_bounds__(256) scores_kernel(
    const float* __restrict__ q, const float* __restrict__ k,
    float* __restrict__ s)
{
    __shared__ float Qs[64][65];   // Qs[d][l], pad 65 -> conflict-free transp. writes
    __shared__ float Ks[64][65];   // Ks[d][m]

    const int b  = blockIdx.z;
    const int l0 = blockIdx.y * 64;
    const int m0 = blockIdx.x * 64;
    const int t  = threadIdx.x;
    const int mx = t & 15;
    const int ly = t >> 4;

    const float* qb = q + (size_t)b * Ln * Dn;
    const float* kb = k + (size_t)b * Ln * Dn;

#pragma unroll
    for (int j = 0; j < 16; j++) {
        int i = t + j * 256;
        int r = i >> 6, d = i & 63;
        Qs[d][r] = qb[(size_t)(l0 + r) * Dn + d];
        Ks[d][r] = kb[(size_t)(m0 + r) * Dn + d];
    }
    __syncthreads();

    float acc[4][4] = {};  // acc[li][mi]
#pragma unroll 8
    for (int d = 0; d < 64; d++) {
        float qa[4], ka[4];
#pragma unroll
        for (int li = 0; li < 4; li++) qa[li] = Qs[d][ly + 16 * li];
#pragma unroll
        for (int mi = 0; mi < 4; mi++) ka[mi] = Ks[d][mx + 16 * mi];
#pragma unroll
        for (int li = 0; li < 4; li++)
#pragma unroll
            for (int mi = 0; mi < 4; mi++)
                acc[li][mi] += qa[li] * ka[mi];
    }

#pragma unroll
    for (int li = 0; li < 4; li++) {
        int l = l0 + ly + 16 * li;
        float* srow = s + ((size_t)b * Ln + l) * Ln + m0;
#pragma unroll
        for (int mi = 0; mi < 4; mi++)
            srow[mx + 16 * mi] = acc[li][mi];
    }
}

// ---------------------------------------------------------------------------
// Kernel 3: in-place row softmax over last dim (L = 2048).
// one block per row (b*L + l), 256 threads, 8 floats each.
// ---------------------------------------------------------------------------
__global__ void __launch_bounds__(256) softmax_kernel(float* __restrict__ s)
{
    float* row = s + (size_t)blockIdx.x * Ln;
    const int t = threadIdx.x;

    float4 v0 = ((const float4*)row)[t];
    float4 v1 = ((const float4*)row)[t + 256];

    float mx = fmaxf(fmaxf(fmaxf(v0.x, v0.y), fmaxf(v0.z, v0.w)),
                     fmaxf(fmaxf(v1.x, v1.y), fmaxf(v1.z, v1.w)));

    __shared__ float red[8];
#pragma unroll
    for (int o = 16; o > 0; o >>= 1)
        mx = fmaxf(mx, __shfl_xor_sync(0xffffffffu, mx, o));
    if ((t & 31) == 0) red[t >> 5] = mx;
    __syncthreads();
    float m = red[0];
#pragma unroll
    for (int i = 1; i < 8; i++) m = fmaxf(m, red[i]);

    v0.x = __expf(v0.x - m); v0.y = __expf(v0.y - m);
    v0.z = __expf(v0.z - m); v0.w = __expf(v0.w - m);
    v1.x = __expf(v1.x - m); v1.y = __expf(v1.y - m);
    v1.z = __expf(v1.z - m); v1.w = __expf(v1.w - m);

    float sum = (v0.x + v0.y) + (v0.z + v0.w) + (v1.x + v1.y) + (v1.z + v1.w);
#pragma unroll
    for (int o = 16; o > 0; o >>= 1)
        sum += __shfl_xor_sync(0xffffffffu, sum, o);
    __syncthreads();                 // red reuse
    if ((t & 31) == 0) red[t >> 5] = sum;
    __syncthreads();
    float tot = 0.f;
#pragma unroll
    for (int i = 0; i < 8; i++) tot += red[i];

    float inv = 1.0f / tot;
    v0.x *= inv; v0.y *= inv; v0.z *= inv; v0.w *= inv;
    v1.x *= inv; v1.y *= inv; v1.z *= inv; v1.w *= inv;
    ((float4*)row)[t]       = v0;
    ((float4*)row)[t + 256] = v1;
}

// ---------------------------------------------------------------------------
// Kernel 4: AV[b][l][c] = sum_m P[b][l][m] * V[b][m][c]
// grid: (C/64, L/64, B), 256 threads.
// ---------------------------------------------------------------------------
__global__ void __launch_bounds__(256) av_kernel(
    const float* __restrict__ p, const float* __restrict__ v,
    float* __restrict__ av)
{
    __shared__ float Ps[16][68];   // Ps[m][l]  (transposed, pad 68)
    __shared__ float Vs[16][64];   // Vs[m][c]  (natural, coalesced)

    const int b  = blockIdx.z;
    const int l0 = blockIdx.y * 64;
    const int c0 = blockIdx.x * 64;
    const int t  = threadIdx.x;
    const int cx = t & 15;
    const int ly = t >> 4;

    const float* pb = p + (size_t)b * Ln * Ln;
    const float* vb = v + (size_t)b * Ln * Cn;
    float acc[4][4] = {};  // acc[li][ci]

    for (int m0 = 0; m0 < Ln; m0 += 16) {
#pragma unroll
        for (int j = 0; j < 4; j++) {
            int i  = t + j * 256;
            int ll = i >> 4, mm = i & 15;
            Ps[mm][ll] = pb[(size_t)(l0 + ll) * Ln + m0 + mm];
            int m2 = i >> 6, cc = i & 63;
            Vs[m2][cc] = vb[(size_t)(m0 + m2) * Cn + c0 + cc];
        }
        __syncthreads();
#pragma unroll
        for (int mm = 0; mm < 16; mm++) {
            float4 pv = *(const float4*)&Ps[mm][ly * 4];
            float4 vv = *(const float4*)&Vs[mm][cx * 4];
            float pa[4] = {pv.x, pv.y, pv.z, pv.w};
            float va[4] = {vv.x, vv.y, vv.z, vv.w};
#pragma unroll
            for (int li = 0; li < 4; li++)
#pragma unroll
                for (int ci = 0; ci < 4; ci++)
                    acc[li][ci] += pa[li] * va[ci];
        }
        __syncthreads();
    }

#pragma unroll
    for (int li = 0; li < 4; li++) {
        int l = l0 + ly * 4 + li;
        float4 r;
        r.x = acc[li][0]; r.y = acc[li][1]; r.z = acc[li][2]; r.w = acc[li][3];
        *(float4*)&av[((size_t)b * Ln + l) * Cn + c0 + cx * 4] = r;
    }
}

// ---------------------------------------------------------------------------
// Kernel 5: out[b][c][l] = gamma * (sum_c' wo[c][c'] * av[b][l][c'] + bo[c]) + x[b][c][l]
// grid: (L/64, C/64, B), 256 threads.
// ---------------------------------------------------------------------------
__global__ void __launch_bounds__(256) out_kernel(
    const float* __restrict__ avp, const float* __restrict__ wo,
    const float* __restrict__ bo, const float* __restrict__ gamma,
    const float* __restrict__ x, float* __restrict__ out)
{
    __shared__ float As[16][68];   // As[c'][l]  from av[l][c']
    __shared__ float Ws[16][68];   // Ws[c'][c]  from wo[c][c']

    const int b  = blockIdx.z;
    const int c0 = blockIdx.y * 64;
    const int l0 = blockIdx.x * 64;
    const int t  = threadIdx.x;
    const int lx = t & 15;          // l group (contiguous store dim)
    const int cy = t >> 4;          // c group

    const float* avb = avp + (size_t)b * Ln * Cn;
    float acc[4][4] = {};  // acc[ci][li]

    for (int k0 = 0; k0 < Cn; k0 += 16) {
#pragma unroll
        for (int j = 0; j < 4; j++) {
            int i  = t + j * 256;
            int rr = i >> 4, kc = i & 15;
            As[kc][rr] = avb[(size_t)(l0 + rr) * Cn + k0 + kc];
            Ws[kc][rr] = wo[(c0 + rr) * Cn + k0 + kc];
        }
        __syncthreads();
#pragma unroll
        for (int kc = 0; kc < 16; kc++) {
            float4 av4 = *(const float4*)&As[kc][lx * 4];
            float4 wv4 = *(const float4*)&Ws[kc][cy * 4];
            float aa[4] = {av4.x, av4.y, av4.z, av4.w};
            float wa[4] = {wv4.x, wv4.y, wv4.z, wv4.w};
#pragma unroll
            for (int ci = 0; ci < 4; ci++)
#pragma unroll
                for (int li = 0; li < 4; li++)
                    acc[ci][li] += wa[ci] * aa[li];
        }
        __syncthreads();
    }

    const float g = gamma[0];
#pragma unroll
    for (int ci = 0; ci < 4; ci++) {
        int c = c0 + cy * 4 + ci;
        float bb = bo[c];
        size_t base = ((size_t)b * Cn + c) * Ln + l0 + lx * 4;
        float4 xr = *(const float4*)&x[base];
        float4 r;
        r.x = g * (acc[ci][0] + bb) + xr.x;
        r.y = g * (acc[ci][1] + bb) + xr.y;
        r.z = g * (acc[ci][2] + bb) + xr.z;
        r.w = g * (acc[ci][3] + bb) + xr.w;
        *(float4*)&out[base] = r;
    }
}

// ---------------------------------------------------------------------------
extern "C" void kernel_launch(void* const* d_in, const int* in_sizes, int n_in,
                              void* d_out, int out_size)
{
    const float* x     = (const float*)d_in[0];
    const float* wq    = (const float*)d_in[1];
    const float* bq    = (const float*)d_in[2];
    const float* wk    = (const float*)d_in[3];
    const float* bk    = (const float*)d_in[4];
    const float* wv    = (const float*)d_in[5];
    const float* bv    = (const float*)d_in[6];
    const float* wo    = (const float*)d_in[7];
    const float* bo    = (const float*)d_in[8];
    const float* gamma = (const float*)d_in[9];
    float* out = (float*)d_out;

    float *q, *k, *v, *attn, *av;
    cudaGetSymbolAddress((void**)&q,    g_q);
    cudaGetSymbolAddress((void**)&k,    g_k);
    cudaGetSymbolAddress((void**)&v,    g_v);
    cudaGetSymbolAddress((void**)&attn, g_attn);
    cudaGetSymbolAddress((void**)&av,   g_av);

    // QKV projections: y[b][l][o]
    conv_blo_kernel<<<dim3(Ln / 64, Dn / 64, Bn), 256>>>(x, wq, bq, q, Dn);
    conv_blo_kernel<<<dim3(Ln / 64, Dn / 64, Bn), 256>>>(x, wk, bk, k, Dn);
    conv_blo_kernel<<<dim3(Ln / 64, Cn / 64, Bn), 256>>>(x, wv, bv, v, Cn);

    // Scores + softmax
    scores_kernel<<<dim3(Ln / 64, Ln / 64, Bn), 256>>>(q, k, attn);
    softmax_kernel<<<Bn * Ln, 256>>>(attn);

    // attn @ V
    av_kernel<<<dim3(Cn / 64, Ln / 64, Bn), 256>>>(attn, v, av);

    // output projection + bias + residual
    out_kernel<<<dim3(Ln / 64, Cn / 64, Bn), 256>>>(av, wo, bo, gamma, x, out);
}

// round 4
// speedup vs baseline: 2.6002x; 2.6002x over previous
#include <cuda_runtime.h>
#include <cuda_bf16.h>
#include <cstdint>

#define Bn 16
#define Cn 512
#define Ln 2048
#define Dn 64

// ---------------------------------------------------------------------------
// Scratch (device globals — no allocation allowed)
// ---------------------------------------------------------------------------
__device__ float g_xt[(size_t)Bn * Ln * Cn];     // x transposed [B][L][C]
__device__ float g_q[(size_t)Bn * Ln * Dn];      // [B][L][D]
__device__ float g_k[(size_t)Bn * Ln * Dn];      // [B][L][D]
__device__ float g_v[(size_t)Bn * Cn * Ln];      // v_t [B][C][L]
__device__ float g_attn[(size_t)Bn * Ln * Ln];   // [B][L][L]
__device__ float g_av[(size_t)Bn * Ln * Cn];     // [B][L][C]

// ---------------------------------------------------------------------------
// Helpers
// ---------------------------------------------------------------------------
__device__ __forceinline__ uint32_t smem_u32(const void* p) {
    uint32_t a;
    asm("{ .reg .u64 t; cvta.to.shared.u64 t, %1; cvt.u32.u64 %0, t; }"
        : "=r"(a) : "l"(p));
    return a;
}

__device__ __forceinline__ void ldm4(uint32_t& r0, uint32_t& r1, uint32_t& r2,
                                     uint32_t& r3, uint32_t addr) {
    asm volatile("ldmatrix.sync.aligned.m8n8.x4.shared.b16 {%0,%1,%2,%3}, [%4];"
                 : "=r"(r0), "=r"(r1), "=r"(r2), "=r"(r3) : "r"(addr));
}

__device__ __forceinline__ void mma16816(float* c, const uint32_t* a,
                                         const uint32_t* b) {
    asm volatile(
        "mma.sync.aligned.m16n8k16.row.col.f32.bf16.bf16.f32 "
        "{%0,%1,%2,%3}, {%4,%5,%6,%7}, {%8,%9}, {%0,%1,%2,%3};"
        : "+f"(c[0]), "+f"(c[1]), "+f"(c[2]), "+f"(c[3])
        : "r"(a[0]), "r"(a[1]), "r"(a[2]), "r"(a[3]), "r"(b[0]), "r"(b[1]));
}

// Split fp32x4 -> hi/lo bf16x4 (8B each), write to smem pointers.
__device__ __forceinline__ void store_split(char* hi_p, char* lo_p, float4 v) {
    __nv_bfloat16 h0 = __float2bfloat16_rn(v.x);
    __nv_bfloat16 h1 = __float2bfloat16_rn(v.y);
    __nv_bfloat16 h2 = __float2bfloat16_rn(v.z);
    __nv_bfloat16 h3 = __float2bfloat16_rn(v.w);
    __nv_bfloat16 l0 = __float2bfloat16_rn(v.x - __bfloat162float(h0));
    __nv_bfloat16 l1 = __float2bfloat16_rn(v.y - __bfloat162float(h1));
    __nv_bfloat16 l2 = __float2bfloat16_rn(v.z - __bfloat162float(h2));
    __nv_bfloat16 l3 = __float2bfloat16_rn(v.w - __bfloat162float(h3));
    uint2 hi, lo;
    hi.x = (uint32_t)__bfloat16_as_ushort(h0) | ((uint32_t)__bfloat16_as_ushort(h1) << 16);
    hi.y = (uint32_t)__bfloat16_as_ushort(h2) | ((uint32_t)__bfloat16_as_ushort(h3) << 16);
    lo.x = (uint32_t)__bfloat16_as_ushort(l0) | ((uint32_t)__bfloat16_as_ushort(l1) << 16);
    lo.y = (uint32_t)__bfloat16_as_ushort(l2) | ((uint32_t)__bfloat16_as_ushort(l3) << 16);
    *(uint2*)hi_p = hi;
    *(uint2*)lo_p = lo;
}

// ---------------------------------------------------------------------------
// Generic split-bf16 warp-MMA GEMM: D[m][n] = sum_k A[m][k] * B[n][k]
// Block tile: 128 x NT, K chunk = 32. 8 warps.
// EPI: 0=none  1=+bias[n]  2=+bias[m]  3=gamma*(D+bias[m])+xres
// ---------------------------------------------------------------------------
#define ROWB 80   // bytes per smem row: 32 bf16 (64B) + 16B pad

template <int NT, int EPI>
__global__ void __launch_bounds__(256, 2) mma_gemm(
    const float* __restrict__ A, const float* __restrict__ B, float* __restrict__ D,
    int K, int lda, int ldb, int ldd,
    size_t sA, size_t sB, size_t sD,
    const float* __restrict__ bias, const float* __restrict__ gamma,
    const float* __restrict__ xres)
{
    extern __shared__ char smem[];
    constexpr int WGM = (NT == 128) ? 2 : 4;   // warps along M
    constexpr int WM  = 128 / WGM;             // 64 or 32 rows per warp
    constexpr int WN  = 32;                    // cols per warp
    constexpr int MI  = WM / 16;               // m16 tiles per warp
    constexpr int NI  = WN / 8;                // n8 tiles per warp

    const int t = threadIdx.x, wid = t >> 5, lane = t & 31;
    const int wm = wid % WGM, wn = wid / WGM;
    const int b = blockIdx.z;
    const int n0 = blockIdx.x * NT;
    const int m0 = blockIdx.y * 128;

    // smem regions (bytes)
    const uint32_t AHo = 0;
    const uint32_t ALo = 128 * ROWB;
    const uint32_t BHo = 2 * 128 * ROWB;
    const uint32_t BLo = BHo + NT * ROWB;
    const uint32_t sb = smem_u32(smem);

    const float* Ab = A + (size_t)b * sA;
    const float* Bb = B + (size_t)b * sB;

    float acc[MI][NI][4];
#pragma unroll
    for (int mi = 0; mi < MI; mi++)
#pragma unroll
        for (int ni = 0; ni < NI; ni++)
#pragma unroll
            for (int j = 0; j < 4; j++) acc[mi][ni][j] = 0.f;

    // per-thread ldmatrix address pieces
    const int jj = lane >> 3, rr = lane & 7;
    const uint32_t a_off = (uint32_t)(((jj & 1) * 8 + rr) * ROWB + (jj >> 1) * 16);
    const uint32_t b_off = (uint32_t)(((jj >> 1) * 8 + rr) * ROWB + (jj & 1) * 16);

    const int nchunks = K >> 5;
    for (int ch = 0; ch < nchunks; ch++) {
        const int k0 = ch << 5;
        // Fill A: 128 rows x 8 float4-slots
#pragma unroll
        for (int i = t; i < 128 * 8; i += 256) {
            int r = i >> 3, kq = i & 7;
            float4 v = *(const float4*)(Ab + (size_t)(m0 + r) * lda + k0 + kq * 4);
            store_split(smem + AHo + r * ROWB + kq * 8,
                        smem + ALo + r * ROWB + kq * 8, v);
        }
        // Fill B: NT rows x 8 slots
#pragma unroll
        for (int i = t; i < NT * 8; i += 256) {
            int r = i >> 3, kq = i & 7;
            float4 v = *(const float4*)(Bb + (size_t)(n0 + r) * ldb + k0 + kq * 4);
            store_split(smem + BHo + r * ROWB + kq * 8,
                        smem + BLo + r * ROWB + kq * 8, v);
        }
        __syncthreads();

#pragma unroll
        for (int ks = 0; ks < 2; ks++) {
            const uint32_t kb = ks * 32;   // 16 bf16 = 32 bytes
            // B fragments (hi & lo): NI n8-tiles, 2 tiles per ldmatrix.x4
            uint32_t bh[NI][2], bl[NI][2];
#pragma unroll
            for (int p = 0; p < NI / 2; p++) {
                uint32_t base = (uint32_t)((wn * WN + p * 16) * ROWB) + kb + b_off;
                ldm4(bh[2 * p][0], bh[2 * p][1], bh[2 * p + 1][0], bh[2 * p + 1][1],
                     sb + BHo + base);
                ldm4(bl[2 * p][0], bl[2 * p][1], bl[2 * p + 1][0], bl[2 * p + 1][1],
                     sb + BLo + base);
            }
#pragma unroll
            for (int mi = 0; mi < MI; mi++) {
                uint32_t base = (uint32_t)((wm * WM + mi * 16) * ROWB) + kb + a_off;
                uint32_t ah[4], al[4];
                ldm4(ah[0], ah[1], ah[2], ah[3], sb + AHo + base);
                ldm4(al[0], al[1], al[2], al[3], sb + ALo + base);
#pragma unroll
                for (int ni = 0; ni < NI; ni++) {
                    mma16816(acc[mi][ni], ah, bh[ni]);
                    mma16816(acc[mi][ni], ah, bl[ni]);
                    mma16816(acc[mi][ni], al, bh[ni]);
                }
            }
        }
        __syncthreads();
    }

    // Epilogue
    const float g = (EPI == 3) ? gamma[0] : 1.f;
    const int ncbase = n0 + wn * WN;
#pragma unroll
    for (int mi = 0; mi < MI; mi++) {
        const int r0 = m0 + wm * WM + mi * 16 + (lane >> 2);
        const int r1 = r0 + 8;
        float br0 = 0.f, br1 = 0.f;
        if (EPI >= 2) { br0 = bias[r0]; br1 = bias[r1]; }
        float* d0 = D + (size_t)b * sD + (size_t)r0 * ldd + ncbase;
        float* d1 = D + (size_t)b * sD + (size_t)r1 * ldd + ncbase;
        const float* x0 = (EPI == 3) ? xres + (size_t)b * sD + (size_t)r0 * ldd + ncbase : nullptr;
        const float* x1 = (EPI == 3) ? xres + (size_t)b * sD + (size_t)r1 * ldd + ncbase : nullptr;
#pragma unroll
        for (int ni = 0; ni < NI; ni++) {
            const int nc = ni * 8 + 2 * (lane & 3);
            float2 v0 = make_float2(acc[mi][ni][0], acc[mi][ni][1]);
            float2 v1 = make_float2(acc[mi][ni][2], acc[mi][ni][3]);
            if (EPI == 1) {
                float2 bn = *(const float2*)(bias + ncbase + nc);
                v0.x += bn.x; v0.y += bn.y; v1.x += bn.x; v1.y += bn.y;
            } else if (EPI == 2) {
                v0.x += br0; v0.y += br0; v1.x += br1; v1.y += br1;
            } else if (EPI == 3) {
                float2 xa = *(const float2*)(x0 + nc);
                float2 xb = *(const float2*)(x1 + nc);
                v0.x = g * (v0.x + br0) + xa.x;
                v0.y = g * (v0.y + br0) + xa.y;
                v1.x = g * (v1.x + br1) + xb.x;
                v1.y = g * (v1.y + br1) + xb.y;
            }
            *(float2*)(d0 + nc) = v0;
            *(float2*)(d1 + nc) = v1;
        }
    }
}

// ---------------------------------------------------------------------------
// Transpose x[b][c][l] -> xt[b][l][c]
// ---------------------------------------------------------------------------
__global__ void __launch_bounds__(256) transpose_kernel(
    const float* __restrict__ x, float* __restrict__ xt)
{
    __shared__ float s[64][65];
    const int b = blockIdx.z, l0 = blockIdx.x * 64, c0 = blockIdx.y * 64;
    const int t = threadIdx.x;
    const float* xb = x + (size_t)b * Cn * Ln;
    float* xo = xt + (size_t)b * Ln * Cn;
#pragma unroll
    for (int j = 0; j < 16; j++) {
        int i = t + j * 256;
        int r = i >> 6, cl = i & 63;
        s[r][cl] = xb[(size_t)(c0 + r) * Ln + l0 + cl];
    }
    __syncthreads();
#pragma unroll
    for (int j = 0; j < 16; j++) {
        int i = t + j * 256;
        int r = i >> 6, cc = i & 63;
        xo[(size_t)(l0 + r) * Cn + c0 + cc] = s[cc][r];
    }
}

// ---------------------------------------------------------------------------
// Row softmax over last dim (L = 2048), in place.
// ---------------------------------------------------------------------------
__global__ void __launch_bounds__(256) softmax_kernel(float* __restrict__ s)
{
    float* row = s + (size_t)blockIdx.x * Ln;
    const int t = threadIdx.x;

    float4 v0 = ((const float4*)row)[t];
    float4 v1 = ((const float4*)row)[t + 256];

    float mx = fmaxf(fmaxf(fmaxf(v0.x, v0.y), fmaxf(v0.z, v0.w)),
                     fmaxf(fmaxf(v1.x, v1.y), fmaxf(v1.z, v1.w)));

    __shared__ float red[8];
#pragma unroll
    for (int o = 16; o > 0; o >>= 1)
        mx = fmaxf(mx, __shfl_xor_sync(0xffffffffu, mx, o));
    if ((t & 31) == 0) red[t >> 5] = mx;
    __syncthreads();
    float m = red[0];
#pragma unroll
    for (int i = 1; i < 8; i++) m = fmaxf(m, red[i]);

    v0.x = __expf(v0.x - m); v0.y = __expf(v0.y - m);
    v0.z = __expf(v0.z - m); v0.w = __expf(v0.w - m);
    v1.x = __expf(v1.x - m); v1.y = __expf(v1.y - m);
    v1.z = __expf(v1.z - m); v1.w = __expf(v1.w - m);

    float sum = (v0.x + v0.y) + (v0.z + v0.w) + (v1.x + v1.y) + (v1.z + v1.w);
#pragma unroll
    for (int o = 16; o > 0; o >>= 1)
        sum += __shfl_xor_sync(0xffffffffu, sum, o);
    __syncthreads();
    if ((t & 31) == 0) red[t >> 5] = sum;
    __syncthreads();
    float tot = 0.f;
#pragma unroll
    for (int i = 0; i < 8; i++) tot += red[i];

    float inv = 1.0f / tot;
    v0.x *= inv; v0.y *= inv; v0.z *= inv; v0.w *= inv;
    v1.x *= inv; v1.y *= inv; v1.z *= inv; v1.w *= inv;
    ((float4*)row)[t]       = v0;
    ((float4*)row)[t + 256] = v1;
}

// ---------------------------------------------------------------------------
extern "C" void kernel_launch(void* const* d_in, const int* in_sizes, int n_in,
                              void* d_out, int out_size)
{
    const float* x     = (const float*)d_in[0];
    const float* wq    = (const float*)d_in[1];
    const float* bq    = (const float*)d_in[2];
    const float* wk    = (const float*)d_in[3];
    const float* bk    = (const float*)d_in[4];
    const float* wv    = (const float*)d_in[5];
    const float* bv    = (const float*)d_in[6];
    const float* wo    = (const float*)d_in[7];
    const float* bo    = (const float*)d_in[8];
    const float* gamma = (const float*)d_in[9];
    float* out = (float*)d_out;

    float *xt, *q, *k, *v, *attn, *av;
    cudaGetSymbolAddress((void**)&xt,   g_xt);
    cudaGetSymbolAddress((void**)&q,    g_q);
    cudaGetSymbolAddress((void**)&k,    g_k);
    cudaGetSymbolAddress((void**)&v,    g_v);
    cudaGetSymbolAddress((void**)&attn, g_attn);
    cudaGetSymbolAddress((void**)&av,   g_av);

    const int SM128 = 2 * 128 * ROWB + 2 * 128 * ROWB;  // 40960 B
    const int SM64  = 2 * 128 * ROWB + 2 * 64 * ROWB;   // 30720 B
    cudaFuncSetAttribute(mma_gemm<64, 1>,  cudaFuncAttributeMaxDynamicSharedMemorySize, SM64);
    cudaFuncSetAttribute(mma_gemm<128, 0>, cudaFuncAttributeMaxDynamicSharedMemorySize, SM128);
    cudaFuncSetAttribute(mma_gemm<128, 2>, cudaFuncAttributeMaxDynamicSharedMemorySize, SM128);
    cudaFuncSetAttribute(mma_gemm<128, 3>, cudaFuncAttributeMaxDynamicSharedMemorySize, SM128);

    const size_t sLC = (size_t)Ln * Cn;
    const size_t sLD = (size_t)Ln * Dn;
    const size_t sLL = (size_t)Ln * Ln;

    // 0) transpose x -> xt[b][l][c]
    transpose_kernel<<<dim3(Ln / 64, Cn / 64, Bn), 256>>>(x, xt);

    // 1) Q/K proj: q[l][d] = xt[l]·wq[d] + bq[d]
    mma_gemm<64, 1><<<dim3(1, Ln / 128, Bn), 256, SM64>>>(
        xt, wq, q, Cn, Cn, Cn, Dn, sLC, 0, sLD, bq, nullptr, nullptr);
    mma_gemm<64, 1><<<dim3(1, Ln / 128, Bn), 256, SM64>>>(
        xt, wk, k, Cn, Cn, Cn, Dn, sLC, 0, sLD, bk, nullptr, nullptr);

    // 2) V proj (transposed output): v_t[c][l] = wv[c]·xt[l] + bv[c]
    mma_gemm<128, 2><<<dim3(Ln / 128, Cn / 128, Bn), 256, SM128>>>(
        wv, xt, v, Cn, Cn, Cn, Ln, 0, sLC, sLC, bv, nullptr, nullptr);

    // 3) scores: S[l][m] = q[l]·k[m]
    mma_gemm<128, 0><<<dim3(Ln / 128, Ln / 128, Bn), 256, SM128>>>(
        q, k, attn, Dn, Dn, Dn, Ln, sLD, sLD, sLL, nullptr, nullptr, nullptr);

    // 4) softmax rows
    softmax_kernel<<<Bn * Ln, 256>>>(attn);

    // 5) AV: av[l][c] = P[l]·v_t[c]
    mma_gemm<128, 0><<<dim3(Cn / 128, Ln / 128, Bn), 256, SM128>>>(
        attn, v, av, Ln, Ln, Ln, Cn, sLL, sLC, sLC, nullptr, nullptr, nullptr);

    // 6) out: out[c][l] = gamma*(wo[c]·av[l] + bo[c]) + x[c][l]
    mma_gemm<128, 3><<<dim3(Ln / 128, Cn / 128, Bn), 256, SM128>>>(
        wo, av, out, Cn, Cn, Cn, Ln, 0, sLC, sLC, bo, gamma, x);
}

// round 5
// speedup vs baseline: 3.7511x; 1.4426x over previous
#include <cuda_runtime.h>
#include <cuda_bf16.h>
#include <cstdint>

#define Bn 16
#define Cn 512
#define Ln 2048
#define Dn 64

// ---------------------------------------------------------------------------
// Scratch (device globals — no allocation allowed)
// ---------------------------------------------------------------------------
__device__ float g_xt[(size_t)Bn * Ln * Cn];     // x transposed [B][L][C]
__device__ float g_q[(size_t)Bn * Ln * Dn];      // [B][L][D]
__device__ float g_k[(size_t)Bn * Ln * Dn];      // [B][L][D]
__device__ float g_v[(size_t)Bn * Cn * Ln];      // v_t [B][C][L]
__device__ float g_attn[(size_t)Bn * Ln * Ln];   // [B][L][L]
__device__ float g_av[(size_t)Bn * Ln * Cn];     // [B][L][C]

// ---------------------------------------------------------------------------
// Helpers
// ---------------------------------------------------------------------------
__device__ __forceinline__ uint32_t smem_u32(const void* p) {
    uint32_t a;
    asm("{ .reg .u64 t; cvta.to.shared.u64 t, %1; cvt.u32.u64 %0, t; }"
        : "=r"(a) : "l"(p));
    return a;
}

__device__ __forceinline__ void ldm4(uint32_t& r0, uint32_t& r1, uint32_t& r2,
                                     uint32_t& r3, uint32_t addr) {
    asm volatile("ldmatrix.sync.aligned.m8n8.x4.shared.b16 {%0,%1,%2,%3}, [%4];"
                 : "=r"(r0), "=r"(r1), "=r"(r2), "=r"(r3) : "r"(addr));
}

__device__ __forceinline__ void mma16816(float* c, const uint32_t* a,
                                         const uint32_t* b) {
    asm volatile(
        "mma.sync.aligned.m16n8k16.row.col.f32.bf16.bf16.f32 "
        "{%0,%1,%2,%3}, {%4,%5,%6,%7}, {%8,%9}, {%0,%1,%2,%3};"
        : "+f"(c[0]), "+f"(c[1]), "+f"(c[2]), "+f"(c[3])
        : "r"(a[0]), "r"(a[1]), "r"(a[2]), "r"(a[3]), "r"(b[0]), "r"(b[1]));
}

// Split fp32x4 -> hi/lo bf16x4 (8B each).
__device__ __forceinline__ void store_split(char* hi_p, char* lo_p, float4 v) {
    __nv_bfloat16 h0 = __float2bfloat16_rn(v.x);
    __nv_bfloat16 h1 = __float2bfloat16_rn(v.y);
    __nv_bfloat16 h2 = __float2bfloat16_rn(v.z);
    __nv_bfloat16 h3 = __float2bfloat16_rn(v.w);
    __nv_bfloat16 l0 = __float2bfloat16_rn(v.x - __bfloat162float(h0));
    __nv_bfloat16 l1 = __float2bfloat16_rn(v.y - __bfloat162float(h1));
    __nv_bfloat16 l2 = __float2bfloat16_rn(v.z - __bfloat162float(h2));
    __nv_bfloat16 l3 = __float2bfloat16_rn(v.w - __bfloat162float(h3));
    uint2 hi, lo;
    hi.x = (uint32_t)__bfloat16_as_ushort(h0) | ((uint32_t)__bfloat16_as_ushort(h1) << 16);
    hi.y = (uint32_t)__bfloat16_as_ushort(h2) | ((uint32_t)__bfloat16_as_ushort(h3) << 16);
    lo.x = (uint32_t)__bfloat16_as_ushort(l0) | ((uint32_t)__bfloat16_as_ushort(l1) << 16);
    lo.y = (uint32_t)__bfloat16_as_ushort(l2) | ((uint32_t)__bfloat16_as_ushort(l3) << 16);
    *(uint2*)hi_p = hi;
    *(uint2*)lo_p = lo;
}

// Plain fp32x4 -> bf16x4 (8B).
__device__ __forceinline__ void store_hi(char* hi_p, float4 v) {
    __nv_bfloat16 h0 = __float2bfloat16_rn(v.x);
    __nv_bfloat16 h1 = __float2bfloat16_rn(v.y);
    __nv_bfloat16 h2 = __float2bfloat16_rn(v.z);
    __nv_bfloat16 h3 = __float2bfloat16_rn(v.w);
    uint2 hi;
    hi.x = (uint32_t)__bfloat16_as_ushort(h0) | ((uint32_t)__bfloat16_as_ushort(h1) << 16);
    hi.y = (uint32_t)__bfloat16_as_ushort(h2) | ((uint32_t)__bfloat16_as_ushort(h3) << 16);
    *(uint2*)hi_p = hi;
}

// ---------------------------------------------------------------------------
// Generic warp-MMA GEMM: D[m][n] = sum_k A[m][k] * B[n][k]
// Block tile 128 x NT, K chunk = 32, 8 warps, double-buffered smem with
// register prefetch. SPLIT: 3-MMA split-bf16 (hi+lo) vs plain bf16.
// EPI: 0=none  1=+bias[n]  2=+bias[m]  3=gamma*(D+bias[m])+xres
// ---------------------------------------------------------------------------
#define ROWB 80   // bytes per smem row: 32 bf16 (64B) + 16B pad

template <int NT, int EPI, bool SPLIT>
__global__ void __launch_bounds__(256, 2) mma_gemm(
    const float* __restrict__ A, const float* __restrict__ B, float* __restrict__ D,
    int K, int lda, int ldb, int ldd,
    size_t sA, size_t sB, size_t sD,
    const float* __restrict__ bias, const float* __restrict__ gamma,
    const float* __restrict__ xres)
{
    extern __shared__ char smem[];
    constexpr int WGM = (NT == 128) ? 2 : 4;
    constexpr int WM  = 128 / WGM;
    constexpr int WN  = 32;
    constexpr int MI  = WM / 16;
    constexpr int NI  = WN / 8;
    constexpr int NAB = SPLIT ? 2 : 1;
    constexpr uint32_t ASZ = 128 * ROWB;
    constexpr uint32_t BSZ = NT * ROWB;
    constexpr uint32_t STG = NAB * (ASZ + BSZ);   // bytes per stage
    constexpr int AJ = 4;          // A fill iters: 128*8/256
    constexpr int BJ = NT / 32;    // B fill iters: NT*8/256

    const int t = threadIdx.x, wid = t >> 5, lane = t & 31;
    const int wm = wid % WGM, wn = wid / WGM;
    const int b = blockIdx.z;
    const int n0 = blockIdx.x * NT;
    const int m0 = blockIdx.y * 128;
    const uint32_t sb = smem_u32(smem);

    const float* Ab = A + (size_t)b * sA;
    const float* Bb = B + (size_t)b * sB;

    float acc[MI][NI][4];
#pragma unroll
    for (int mi = 0; mi < MI; mi++)
#pragma unroll
        for (int ni = 0; ni < NI; ni++)
#pragma unroll
            for (int j = 0; j < 4; j++) acc[mi][ni][j] = 0.f;

    const int jj = lane >> 3, rr = lane & 7;
    const uint32_t a_off = (uint32_t)(((jj & 1) * 8 + rr) * ROWB + (jj >> 1) * 16);
    const uint32_t b_off = (uint32_t)(((jj >> 1) * 8 + rr) * ROWB + (jj & 1) * 16);

    float4 pa[AJ], pb[BJ];

    auto ldA = [&](int k0) {
#pragma unroll
        for (int j = 0; j < AJ; j++) {
            int i = t + j * 256, r = i >> 3, kq = i & 7;
            pa[j] = *(const float4*)(Ab + (size_t)(m0 + r) * lda + k0 + kq * 4);
        }
    };
    auto ldB = [&](int k0) {
#pragma unroll
        for (int j = 0; j < BJ; j++) {
            int i = t + j * 256, r = i >> 3, kq = i & 7;
            pb[j] = *(const float4*)(Bb + (size_t)(n0 + r) * ldb + k0 + kq * 4);
        }
    };
    auto stAB = [&](int s) {
        char* abase = smem + (uint32_t)s * STG;
        char* bbase = abase + NAB * ASZ;
#pragma unroll
        for (int j = 0; j < AJ; j++) {
            int i = t + j * 256, r = i >> 3, kq = i & 7;
            if (SPLIT)
                store_split(abase + r * ROWB + kq * 8, abase + ASZ + r * ROWB + kq * 8, pa[j]);
            else
                store_hi(abase + r * ROWB + kq * 8, pa[j]);
        }
#pragma unroll
        for (int j = 0; j < BJ; j++) {
            int i = t + j * 256, r = i >> 3, kq = i & 7;
            if (SPLIT)
                store_split(bbase + r * ROWB + kq * 8, bbase + BSZ + r * ROWB + kq * 8, pb[j]);
            else
                store_hi(bbase + r * ROWB + kq * 8, pb[j]);
        }
    };
    auto mmaS = [&](int s) {
        const uint32_t AH = (uint32_t)s * STG;
        const uint32_t AL = AH + ASZ;
        const uint32_t BH = AH + NAB * ASZ;
        const uint32_t BL = BH + BSZ;
#pragma unroll
        for (int ks = 0; ks < 2; ks++) {
            const uint32_t kb = ks * 32;
            uint32_t bh[NI][2], bl[NI][2];
#pragma unroll
            for (int p = 0; p < NI / 2; p++) {
                uint32_t bse = (uint32_t)((wn * WN + p * 16) * ROWB) + kb + b_off;
                ldm4(bh[2 * p][0], bh[2 * p][1], bh[2 * p + 1][0], bh[2 * p + 1][1],
                     sb + BH + bse);
                if (SPLIT)
                    ldm4(bl[2 * p][0], bl[2 * p][1], bl[2 * p + 1][0], bl[2 * p + 1][1],
                         sb + BL + bse);
            }
#pragma unroll
            for (int mi = 0; mi < MI; mi++) {
                uint32_t ase = (uint32_t)((wm * WM + mi * 16) * ROWB) + kb + a_off;
                uint32_t ah[4], al[4];
                ldm4(ah[0], ah[1], ah[2], ah[3], sb + AH + ase);
                if (SPLIT) ldm4(al[0], al[1], al[2], al[3], sb + AL + ase);
#pragma unroll
                for (int ni = 0; ni < NI; ni++) {
                    mma16816(acc[mi][ni], ah, bh[ni]);
                    if (SPLIT) {
                        mma16816(acc[mi][ni], ah, bl[ni]);
                        mma16816(acc[mi][ni], al, bh[ni]);
                    }
                }
            }
        }
    };

    // Pipelined mainloop (2 stages, 1 sync per chunk)
    const int nch = K >> 5;
    ldA(0); ldB(0);
    stAB(0);
    __syncthreads();
    for (int ch = 0; ch < nch; ch++) {
        if (ch + 1 < nch) { ldA((ch + 1) << 5); ldB((ch + 1) << 5); }
        mmaS(ch & 1);
        if (ch + 1 < nch) stAB((ch + 1) & 1);
        __syncthreads();
    }

    // Epilogue
    const float g = (EPI == 3) ? gamma[0] : 1.f;
    const int ncbase = n0 + wn * WN;
#pragma unroll
    for (int mi = 0; mi < MI; mi++) {
        const int r0 = m0 + wm * WM + mi * 16 + (lane >> 2);
        const int r1 = r0 + 8;
        float br0 = 0.f, br1 = 0.f;
        if (EPI >= 2) { br0 = bias[r0]; br1 = bias[r1]; }
        float* d0 = D + (size_t)b * sD + (size_t)r0 * ldd + ncbase;
        float* d1 = D + (size_t)b * sD + (size_t)r1 * ldd + ncbase;
        const float* x0 = (EPI == 3) ? xres + (size_t)b * sD + (size_t)r0 * ldd + ncbase : nullptr;
        const float* x1 = (EPI == 3) ? xres + (size_t)b * sD + (size_t)r1 * ldd + ncbase : nullptr;
#pragma unroll
        for (int ni = 0; ni < NI; ni++) {
            const int nc = ni * 8 + 2 * (lane & 3);
            float2 v0 = make_float2(acc[mi][ni][0], acc[mi][ni][1]);
            float2 v1 = make_float2(acc[mi][ni][2], acc[mi][ni][3]);
            if (EPI == 1) {
                float2 bn = *(const float2*)(bias + ncbase + nc);
                v0.x += bn.x; v0.y += bn.y; v1.x += bn.x; v1.y += bn.y;
            } else if (EPI == 2) {
                v0.x += br0; v0.y += br0; v1.x += br1; v1.y += br1;
            } else if (EPI == 3) {
                float2 xa = *(const float2*)(x0 + nc);
                float2 xb = *(const float2*)(x1 + nc);
                v0.x = g * (v0.x + br0) + xa.x;
                v0.y = g * (v0.y + br0) + xa.y;
                v1.x = g * (v1.x + br1) + xb.x;
                v1.y = g * (v1.y + br1) + xb.y;
            }
            *(float2*)(d0 + nc) = v0;
            *(float2*)(d1 + nc) = v1;
        }
    }
}

// ---------------------------------------------------------------------------
// Transpose x[b][c][l] -> xt[b][l][c]
// ---------------------------------------------------------------------------
__global__ void __launch_bounds__(256) transpose_kernel(
    const float* __restrict__ x, float* __restrict__ xt)
{
    __shared__ float s[64][65];
    const int b = blockIdx.z, l0 = blockIdx.x * 64, c0 = blockIdx.y * 64;
    const int t = threadIdx.x;
    const float* xb = x + (size_t)b * Cn * Ln;
    float* xo = xt + (size_t)b * Ln * Cn;
#pragma unroll
    for (int j = 0; j < 16; j++) {
        int i = t + j * 256;
        int r = i >> 6, cl = i & 63;
        s[r][cl] = xb[(size_t)(c0 + r) * Ln + l0 + cl];
    }
    __syncthreads();
#pragma unroll
    for (int j = 0; j < 16; j++) {
        int i = t + j * 256;
        int r = i >> 6, cc = i & 63;
        xo[(size_t)(l0 + r) * Cn + c0 + cc] = s[cc][r];
    }
}

// ---------------------------------------------------------------------------
// Row softmax over last dim (L = 2048), in place.
// ---------------------------------------------------------------------------
__global__ void __launch_bounds__(256) softmax_kernel(float* __restrict__ s)
{
    float* row = s + (size_t)blockIdx.x * Ln;
    const int t = threadIdx.x;

    float4 v0 = ((const float4*)row)[t];
    float4 v1 = ((const float4*)row)[t + 256];

    float mx = fmaxf(fmaxf(fmaxf(v0.x, v0.y), fmaxf(v0.z, v0.w)),
                     fmaxf(fmaxf(v1.x, v1.y), fmaxf(v1.z, v1.w)));

    __shared__ float red[8];
#pragma unroll
    for (int o = 16; o > 0; o >>= 1)
        mx = fmaxf(mx, __shfl_xor_sync(0xffffffffu, mx, o));
    if ((t & 31) == 0) red[t >> 5] = mx;
    __syncthreads();
    float m = red[0];
#pragma unroll
    for (int i = 1; i < 8; i++) m = fmaxf(m, red[i]);

    v0.x = __expf(v0.x - m); v0.y = __expf(v0.y - m);
    v0.z = __expf(v0.z - m); v0.w = __expf(v0.w - m);
    v1.x = __expf(v1.x - m); v1.y = __expf(v1.y - m);
    v1.z = __expf(v1.z - m); v1.w = __expf(v1.w - m);

    float sum = (v0.x + v0.y) + (v0.z + v0.w) + (v1.x + v1.y) + (v1.z + v1.w);
#pragma unroll
    for (int o = 16; o > 0; o >>= 1)
        sum += __shfl_xor_sync(0xffffffffu, sum, o);
    __syncthreads();
    if ((t & 31) == 0) red[t >> 5] = sum;
    __syncthreads();
    float tot = 0.f;
#pragma unroll
    for (int i = 0; i < 8; i++) tot += red[i];

    float inv = 1.0f / tot;
    v0.x *= inv; v0.y *= inv; v0.z *= inv; v0.w *= inv;
    v1.x *= inv; v1.y *= inv; v1.z *= inv; v1.w *= inv;
    ((float4*)row)[t]       = v0;
    ((float4*)row)[t + 256] = v1;
}

// ---------------------------------------------------------------------------
extern "C" void kernel_launch(void* const* d_in, const int* in_sizes, int n_in,
                              void* d_out, int out_size)
{
    const float* x     = (const float*)d_in[0];
    const float* wq    = (const float*)d_in[1];
    const float* bq    = (const float*)d_in[2];
    const float* wk    = (const float*)d_in[3];
    const float* bk    = (const float*)d_in[4];
    const float* wv    = (const float*)d_in[5];
    const float* bv    = (const float*)d_in[6];
    const float* wo    = (const float*)d_in[7];
    const float* bo    = (const float*)d_in[8];
    const float* gamma = (const float*)d_in[9];
    float* out = (float*)d_out;

    float *xt, *q, *k, *v, *attn, *av;
    cudaGetSymbolAddress((void**)&xt,   g_xt);
    cudaGetSymbolAddress((void**)&q,    g_q);
    cudaGetSymbolAddress((void**)&k,    g_k);
    cudaGetSymbolAddress((void**)&v,    g_v);
    cudaGetSymbolAddress((void**)&attn, g_attn);
    cudaGetSymbolAddress((void**)&av,   g_av);

    // smem sizes: 2 stages of NAB*(128+NT)*ROWB
    const int SM_QK  = 2 * (1 * (128 + 64) * ROWB);    // 30720
    const int SM_P   = 2 * (1 * (128 + 128) * ROWB);   // 40960 (plain, NT=128)
    const int SM_S   = 2 * (2 * (128 + 128) * ROWB);   // 81920 (split, NT=128)
    cudaFuncSetAttribute(mma_gemm<64, 1, false>,  cudaFuncAttributeMaxDynamicSharedMemorySize, SM_QK);
    cudaFuncSetAttribute(mma_gemm<128, 2, false>, cudaFuncAttributeMaxDynamicSharedMemorySize, SM_P);
    cudaFuncSetAttribute(mma_gemm<128, 0, false>, cudaFuncAttributeMaxDynamicSharedMemorySize, SM_P);
    cudaFuncSetAttribute(mma_gemm<128, 0, true>,  cudaFuncAttributeMaxDynamicSharedMemorySize, SM_S);
    cudaFuncSetAttribute(mma_gemm<128, 3, true>,  cudaFuncAttributeMaxDynamicSharedMemorySize, SM_S);

    const size_t sLC = (size_t)Ln * Cn;
    const size_t sLD = (size_t)Ln * Dn;
    const size_t sLL = (size_t)Ln * Ln;

    // 0) transpose x -> xt[b][l][c]
    transpose_kernel<<<dim3(Ln / 64, Cn / 64, Bn), 256>>>(x, xt);

    // 1) Q/K proj (plain bf16): q[l][d] = xt[l]·wq[d] + bq[d]
    mma_gemm<64, 1, false><<<dim3(1, Ln / 128, Bn), 256, SM_QK>>>(
        xt, wq, q, Cn, Cn, Cn, Dn, sLC, 0, sLD, bq, nullptr, nullptr);
    mma_gemm<64, 1, false><<<dim3(1, Ln / 128, Bn), 256, SM_QK>>>(
        xt, wk, k, Cn, Cn, Cn, Dn, sLC, 0, sLD, bk, nullptr, nullptr);

    // 2) V proj (plain, transposed output): v_t[c][l] = wv[c]·xt[l] + bv[c]
    mma_gemm<128, 2, false><<<dim3(Ln / 128, Cn / 128, Bn), 256, SM_P>>>(
        wv, xt, v, Cn, Cn, Cn, Ln, 0, sLC, sLC, bv, nullptr, nullptr);

    // 3) scores (split): S[l][m] = q[l]·k[m]
    mma_gemm<128, 0, true><<<dim3(Ln / 128, Ln / 128, Bn), 256, SM_S>>>(
        q, k, attn, Dn, Dn, Dn, Ln, sLD, sLD, sLL, nullptr, nullptr, nullptr);

    // 4) softmax rows
    softmax_kernel<<<Bn * Ln, 256>>>(attn);

    // 5) AV (plain): av[l][c] = P[l]·v_t[c]
    mma_gemm<128, 0, false><<<dim3(Cn / 128, Ln / 128, Bn), 256, SM_P>>>(
        attn, v, av, Ln, Ln, Ln, Cn, sLL, sLC, sLC, nullptr, nullptr, nullptr);

    // 6) out (split): out[c][l] = gamma*(wo[c]·av[l] + bo[c]) + x[c][l]
    mma_gemm<128, 3, true><<<dim3(Ln / 128, Cn / 128, Bn), 256, SM_S>>>(
        wo, av, out, Cn, Cn, Cn, Ln, 0, sLC, sLC, bo, gamma, x);
}